// round 14
// baseline (speedup 1.0000x reference)
#include <cuda_runtime.h>
#include <cstdint>

#define KTAGS 16
#define TLEN  512
#define BROWS 1024
#define START_ID 14
#define STOP_ID  15

__device__ float g_row_out[BROWS];
__device__ int   g_ctr = 0;      // last-block counter, self-resetting

typedef unsigned long long u64;

// ---- f32x2 packed helpers ----
__device__ __forceinline__ u64 pk2(float lo, float hi) {
    u64 r; asm("mov.b64 %0, {%1, %2};" : "=l"(r) : "f"(lo), "f"(hi)); return r;
}
__device__ __forceinline__ u64 mul2(u64 a, u64 b) {
    u64 r; asm("mul.rn.f32x2 %0, %1, %2;" : "=l"(r) : "l"(a), "l"(b)); return r;
}
__device__ __forceinline__ u64 fma2(u64 a, u64 b, u64 c) {
    u64 r; asm("fma.rn.f32x2 %0, %1, %2, %3;" : "=l"(r) : "l"(a), "l"(b), "l"(c)); return r;
}
__device__ __forceinline__ u64 add2(u64 a, u64 b) {
    u64 r; asm("add.rn.f32x2 %0, %1, %2;" : "=l"(r) : "l"(a), "l"(b)); return r;
}
__device__ __forceinline__ float hadd2(u64 a) {
    float lo, hi;
    asm("mov.b64 {%0, %1}, %2;" : "=f"(lo), "=f"(hi) : "l"(a));
    return lo + hi;
}

// ---------------------------------------------------------------------------
// Meet-in-the-middle CRF. One 32-lane warp per batch row:
//   lanes 0-15  : forward chain  p <- eh_t (.) (Etr  p),  t = 0 .. m-1
//   lanes 16-31 : adjoint chain  w <- eh_t (.) (EtrT w),  t = len-2 .. m
// Stitch: score = C_f + C_b + ln( sum_j w_m[j] * (Etr p_m)[j] ).
// Emit addressing via precomputed (ebase, esgn): idx = max(ebase+esgn*sn, 0)
// (fwd upper clamp provably dead: sn <= trip+7 <= 263 < 512).
// ---------------------------------------------------------------------------
__global__ void __launch_bounds__(128)
crf_fused_kernel(const float* __restrict__ h,
                 const int*   __restrict__ y32,      // raw y words (int32 view)
                 const float* __restrict__ mask,
                 const float* __restrict__ trans,
                 float* __restrict__ out) {
    __shared__ float tr_s[256];
    __shared__ __align__(16) float pbuf[2][4][2][16]; // [parity][warp][grp][state]
    __shared__ int   s_ysh;
    __shared__ int   s_last;
    __shared__ float s_red[4];

    const int tid = threadIdx.x;

    if (tid < 64) ((float4*)tr_s)[tid] = ((const float4*)trans)[tid];

    // y dtype detection: int64 layout -> hi 32-bit word of each u64 is 0.
    if (tid < 32) {
        u64 v = ((const u64*)y32)[(size_t)tid * 256];
        unsigned bal = __ballot_sync(0xFFFFFFFFu, (unsigned)(v >> 32) != 0u);
        if (tid == 0) s_ysh = (bal == 0u) ? 1 : 0;
    }
    __syncthreads();

    const int wid   = tid >> 5;          // warp in block (0..3)
    const int lane  = tid & 31;
    const int grp   = lane >> 4;         // 0 = forward, 1 = backward
    const int j     = lane & 15;         // state index
    const int row   = blockIdx.x * 4 + wid;

    const float* hrow = h    + (size_t)row * TLEN * KTAGS;
    const float* mrow = mask + (size_t)row * TLEN;
    const int ysh = s_ysh;
    const int* yrow = y32 + (((size_t)row * TLEN) << ysh);

    // ---- fast length: float4 mask loads (full MLP), one warp reduce ----
    float lsum;
    {
        const float4* m4 = (const float4*)mrow;
        float4 a = m4[lane];
        float4 b = m4[lane + 32];
        float4 c = m4[lane + 64];
        float4 d = m4[lane + 96];
        lsum = (a.x + a.y + a.z + a.w) + (b.x + b.y + b.z + b.w)
             + (c.x + c.y + c.z + c.w) + (d.x + d.y + d.z + d.w);
#pragma unroll
        for (int s = 16; s; s >>= 1)
            lsum += __shfl_xor_sync(0xFFFFFFFFu, lsum, s);
    }
    const int len = (int)(lsum + 0.5f);

    // M row for this lane: fwd -> Etr[j,i] = exp(trans[j,i]);
    //                      bwd -> EtrT[j,i] = exp(trans[i,j]).
    u64 EtrP[8];
#pragma unroll
    for (int k = 0; k < 8; k++) {
        int i0 = 2 * k, i1 = 2 * k + 1;
        float e0 = __expf(grp ? tr_s[i0 * 16 + j] : tr_s[j * 16 + i0]);
        float e1 = __expf(grp ? tr_s[i1 * 16 + j] : tr_s[j * 16 + i1]);
        EtrP[k] = pk2(e0, e1);
    }

    // ---- init per-lane chain state (issues its DRAM load early) ----
    float p;
    if (grp == 0) {
        p = (j == START_ID) ? 1.0f : 0.0f;
    } else {
        p = __expf(hrow[(len - 1) * 16 + j]) * __expf(tr_s[STOP_ID * 16 + j]);
    }
    float C = 0.0f;

    // emit index stream: idx(sn) = max(ebase + esgn*sn, 0)
    const int ebase = grp ? (len - 2) : 0;
    const int esgn  = grp ? -1 : 1;

    // emit prefetch (issues early, overlaps gold pass below)
    float hb[8];
#pragma unroll
    for (int d = 0; d < 8; d++) {
        int idx = max(ebase + esgn * d, 0);
        hb[d] = hrow[idx * 16 + j];
    }

    // ---- gold score: two MLP-8 batches ----
    float gsum = 0.f;
#pragma unroll
    for (int half = 0; half < 2; half++) {
        float mk[8];
        int   yt[8], yp[8];
#pragma unroll
        for (int i = 0; i < 8; i++) {
            int k = lane + (half * 8 + i) * 32;
            mk[i] = mrow[k];
            yt[i] = yrow[k << ysh];
            yp[i] = (k == 0) ? START_ID : yrow[(k - 1) << ysh];
        }
        float ev[8];
#pragma unroll
        for (int i = 0; i < 8; i++) {
            int k = lane + (half * 8 + i) * 32;
            ev[i] = hrow[k * 16 + yt[i]];
        }
#pragma unroll
        for (int i = 0; i < 8; i++)
            gsum = fmaf(mk[i], ev[i] + tr_s[yt[i] * 16 + yp[i]], gsum);
    }
#pragma unroll
    for (int s = 16; s; s >>= 1)
        gsum += __shfl_xor_sync(0xFFFFFFFFu, gsum, s);
    const float gold = gsum + tr_s[STOP_ID * 16 + yrow[(len - 1) << ysh]];

    // split: forward does m steps, backward does len-1-m steps
    const int m    = (len - 1) >> 1;
    const int cntF = m;
    const int cntB = len - 1 - m;
    const int cnt  = grp ? cntB : cntF;          // this lane's active steps
    const int trip = (max(cntF, cntB) + 7) & ~7; // warp-uniform

    for (int s0 = 0; s0 < trip; s0 += 8) {
        float eh[8];
#pragma unroll
        for (int u = 0; u < 8; u++) eh[u] = __expf(hb[u]);
#pragma unroll
        for (int u = 0; u < 8; u++) {
            int idx = max(ebase + esgn * (s0 + u + 8), 0);
            hb[u] = hrow[idx * 16 + j];
        }

        unsigned mu = 0u;       // stale-by-1 lane-local max of exchanged bits

#pragma unroll
        for (int u = 0; u < 8; u++) {
            const bool act = (s0 + u) < cnt;     // per-lane FSEL
            float* buf = pbuf[u & 1][wid][grp];
            buf[j] = p;
            __syncwarp();
            const ulonglong2* bp = (const ulonglong2*)buf;
            const ulonglong2 v0 = bp[0];
            const ulonglong2 v1 = bp[1];
            const ulonglong2 v2 = bp[2];
            const ulonglong2 v3 = bp[3];

            u64 a0 = fma2(v0.y, EtrP[1], mul2(v0.x, EtrP[0]));
            u64 a1 = fma2(v1.y, EtrP[3], mul2(v1.x, EtrP[2]));
            u64 a2 = fma2(v2.y, EtrP[5], mul2(v2.x, EtrP[4]));
            u64 a3 = fma2(v3.y, EtrP[7], mul2(v3.x, EtrP[6]));
            float S = hadd2(add2(add2(a0, a1), add2(a2, a3)));
            float pn = S * eh[u];
            p = act ? pn : p;

            if (u == 7) {
                unsigned m0 = max((unsigned)v0.x, (unsigned)(v0.x >> 32));
                unsigned m1 = max((unsigned)v0.y, (unsigned)(v0.y >> 32));
                unsigned m2 = max((unsigned)v1.x, (unsigned)(v1.x >> 32));
                unsigned m3 = max((unsigned)v1.y, (unsigned)(v1.y >> 32));
                unsigned m4 = max((unsigned)v2.x, (unsigned)(v2.x >> 32));
                unsigned m5 = max((unsigned)v2.y, (unsigned)(v2.y >> 32));
                unsigned m6 = max((unsigned)v3.x, (unsigned)(v3.x >> 32));
                unsigned m7 = max((unsigned)v3.y, (unsigned)(v3.y >> 32));
                mu = max(max(max(m0, m1), max(m2, m3)),
                         max(max(m4, m5), max(m6, m7)));
            }
        }
        // exponent-only renorm: exact power-of-2 scaling
        int me = (int)(mu >> 23);
        me = (me < 1) ? 1 : me;
        float scale = __uint_as_float((unsigned)(254 - me) << 23);  // 2^(127-me)
        C += (float)(me - 127) * 0.6931471805599453f;
        p *= scale;
    }

    // ---- stitch: score = C_f + C_b + ln( sum_j w_m[j] * (Etr p_m)[j] ) ----
    {
        float* buf = pbuf[0][wid][grp];
        buf[j] = p;
        __syncwarp();
        const ulonglong2* bp = (const ulonglong2*)buf;
        const ulonglong2 v0 = bp[0];
        const ulonglong2 v1 = bp[1];
        const ulonglong2 v2 = bp[2];
        const ulonglong2 v3 = bp[3];
        u64 a0 = fma2(v0.y, EtrP[1], mul2(v0.x, EtrP[0]));
        u64 a1 = fma2(v1.y, EtrP[3], mul2(v1.x, EtrP[2]));
        u64 a2 = fma2(v2.y, EtrP[5], mul2(v2.x, EtrP[4]));
        u64 a3 = fma2(v3.y, EtrP[7], mul2(v3.x, EtrP[6]));
        float S = hadd2(add2(add2(a0, a1), add2(a2, a3)));  // fwd lanes: (Etr p_m)[j]

        float wsw = __shfl_xor_sync(0xFFFFFFFFu, p, 16);    // fwd lane j <- w_m[j]
        float Csw = __shfl_xor_sync(0xFFFFFFFFu, C, 16);    // fwd lane <- C_b

        float v = S * wsw;
#pragma unroll
        for (int s = 8; s; s >>= 1)
            v += __shfl_xor_sync(0xFFFFFFFFu, v, s, 16);

        if (lane == 0) {
            float fwd = C + Csw + __logf(v);
            g_row_out[row] = fwd - gold;
        }
    }

    // ---- last-block mean reduction ----
    __threadfence();
    __syncthreads();
    if (tid == 0) {
        int old = atomicAdd(&g_ctr, 1);
        s_last = (old == gridDim.x - 1);
    }
    __syncthreads();
    if (s_last) {
        float s = 0.f;
#pragma unroll
        for (int i = 0; i < BROWS / 128; i++)
            s += g_row_out[tid + i * 128];
#pragma unroll
        for (int sft = 16; sft; sft >>= 1)
            s += __shfl_xor_sync(0xFFFFFFFFu, s, sft);
        if ((tid & 31) == 0) s_red[tid >> 5] = s;
        __syncthreads();
        if (tid == 0) {
            float tot = s_red[0] + s_red[1] + s_red[2] + s_red[3];
            out[0] = tot * (1.0f / (float)BROWS);
            g_ctr = 0;   // reset for next graph replay
        }
    }
}

// ---------------------------------------------------------------------------
extern "C" void kernel_launch(void* const* d_in, const int* in_sizes, int n_in,
                              void* d_out, int out_size) {
    const float* h     = (const float*)d_in[0];
    const int*   y     = (const int*)d_in[1];
    const float* mask  = (const float*)d_in[2];
    const float* trans = (const float*)d_in[3];
    float* out = (float*)d_out;

    crf_fused_kernel<<<BROWS / 4, 128>>>(h, y, mask, trans, out);
}

// round 15
// speedup vs baseline: 1.0490x; 1.0490x over previous
#include <cuda_runtime.h>
#include <cstdint>

#define KTAGS 16
#define TLEN  512
#define BROWS 1024
#define START_ID 14
#define STOP_ID  15

__device__ float g_row_out[BROWS];
__device__ int   g_ctr = 0;      // last-block counter, self-resetting

typedef unsigned long long u64;

// ---- f32x2 packed helpers ----
__device__ __forceinline__ u64 pk2(float lo, float hi) {
    u64 r; asm("mov.b64 %0, {%1, %2};" : "=l"(r) : "f"(lo), "f"(hi)); return r;
}
__device__ __forceinline__ u64 mul2(u64 a, u64 b) {
    u64 r; asm("mul.rn.f32x2 %0, %1, %2;" : "=l"(r) : "l"(a), "l"(b)); return r;
}
__device__ __forceinline__ u64 fma2(u64 a, u64 b, u64 c) {
    u64 r; asm("fma.rn.f32x2 %0, %1, %2, %3;" : "=l"(r) : "l"(a), "l"(b), "l"(c)); return r;
}
__device__ __forceinline__ u64 add2(u64 a, u64 b) {
    u64 r; asm("add.rn.f32x2 %0, %1, %2;" : "=l"(r) : "l"(a), "l"(b)); return r;
}
__device__ __forceinline__ float hadd2(u64 a) {
    float lo, hi;
    asm("mov.b64 {%0, %1}, %2;" : "=f"(lo), "=f"(hi) : "l"(a));
    return lo + hi;
}

// ---------------------------------------------------------------------------
// Meet-in-the-middle CRF. One 32-lane warp per batch row:
//   lanes 0-15  : forward chain  p <- eh_t (.) (Etr  p),  t = 0 .. m-1
//   lanes 16-31 : adjoint chain  w <- eh_t (.) (EtrT w),  t = len-2 .. m
// Stitch: score = C_f + C_b + ln( sum_j w_m[j] * (Etr p_m)[j] ).
// Rotating emit pipeline: one __expf (for t+8) and one LDG (for t+16) per
// step instead of 8+8 bursts at block boundaries.
// ---------------------------------------------------------------------------
__global__ void __launch_bounds__(128)
crf_fused_kernel(const float* __restrict__ h,
                 const int*   __restrict__ y32,      // raw y words (int32 view)
                 const float* __restrict__ mask,
                 const float* __restrict__ trans,
                 float* __restrict__ out) {
    __shared__ float tr_s[256];
    __shared__ __align__(16) float pbuf[2][4][2][16]; // [parity][warp][grp][state]
    __shared__ int   s_ysh;
    __shared__ int   s_last;
    __shared__ float s_red[4];

    const int tid = threadIdx.x;

    if (tid < 64) ((float4*)tr_s)[tid] = ((const float4*)trans)[tid];

    // y dtype detection: int64 layout -> hi 32-bit word of each u64 is 0.
    if (tid < 32) {
        u64 v = ((const u64*)y32)[(size_t)tid * 256];
        unsigned bal = __ballot_sync(0xFFFFFFFFu, (unsigned)(v >> 32) != 0u);
        if (tid == 0) s_ysh = (bal == 0u) ? 1 : 0;
    }
    __syncthreads();

    const int wid   = tid >> 5;          // warp in block (0..3)
    const int lane  = tid & 31;
    const int grp   = lane >> 4;         // 0 = forward, 1 = backward
    const int j     = lane & 15;         // state index
    const int row   = blockIdx.x * 4 + wid;

    const float* hrow = h    + (size_t)row * TLEN * KTAGS;
    const float* mrow = mask + (size_t)row * TLEN;
    const int ysh = s_ysh;
    const int* yrow = y32 + (((size_t)row * TLEN) << ysh);

    // ---- fast length: float4 mask loads (full MLP), one warp reduce ----
    float lsum;
    {
        const float4* m4 = (const float4*)mrow;
        float4 a = m4[lane];
        float4 b = m4[lane + 32];
        float4 c = m4[lane + 64];
        float4 d = m4[lane + 96];
        lsum = (a.x + a.y + a.z + a.w) + (b.x + b.y + b.z + b.w)
             + (c.x + c.y + c.z + c.w) + (d.x + d.y + d.z + d.w);
#pragma unroll
        for (int s = 16; s; s >>= 1)
            lsum += __shfl_xor_sync(0xFFFFFFFFu, lsum, s);
    }
    const int len = (int)(lsum + 0.5f);

    // M row for this lane: fwd -> Etr[j,i] = exp(trans[j,i]);
    //                      bwd -> EtrT[j,i] = exp(trans[i,j]).
    u64 EtrP[8];
#pragma unroll
    for (int k = 0; k < 8; k++) {
        int i0 = 2 * k, i1 = 2 * k + 1;
        float e0 = __expf(grp ? tr_s[i0 * 16 + j] : tr_s[j * 16 + i0]);
        float e1 = __expf(grp ? tr_s[i1 * 16 + j] : tr_s[j * 16 + i1]);
        EtrP[k] = pk2(e0, e1);
    }

    // ---- init per-lane chain state (issues its DRAM load early) ----
    float p;
    if (grp == 0) {
        p = (j == START_ID) ? 1.0f : 0.0f;
    } else {
        p = __expf(hrow[(len - 1) * 16 + j]) * __expf(tr_s[STOP_ID * 16 + j]);
    }
    float C = 0.0f;

    // emit index stream: idx(sn) = max(ebase + esgn*sn, 0)
    // (fwd upper bound: sn <= trip-1+16 <= 271 < 512, no clamp needed)
    const int ebase = grp ? (len - 2) : 0;
    const int esgn  = grp ? -1 : 1;

    // rotating pipelines: ehq[d] = exp(emit) for step s0+d,
    //                     hb[d]  = raw emit for step s0+d+8
    float ehq[8], hb[8];
#pragma unroll
    for (int d = 0; d < 8; d++)
        ehq[d] = __expf(hrow[max(ebase + esgn * d, 0) * 16 + j]);
#pragma unroll
    for (int d = 0; d < 8; d++)
        hb[d] = hrow[max(ebase + esgn * (d + 8), 0) * 16 + j];

    // ---- gold score: two MLP-8 batches ----
    float gsum = 0.f;
#pragma unroll
    for (int half = 0; half < 2; half++) {
        float mk[8];
        int   yt[8], yp[8];
#pragma unroll
        for (int i = 0; i < 8; i++) {
            int k = lane + (half * 8 + i) * 32;
            mk[i] = mrow[k];
            yt[i] = yrow[k << ysh];
            yp[i] = (k == 0) ? START_ID : yrow[(k - 1) << ysh];
        }
        float ev[8];
#pragma unroll
        for (int i = 0; i < 8; i++) {
            int k = lane + (half * 8 + i) * 32;
            ev[i] = hrow[k * 16 + yt[i]];
        }
#pragma unroll
        for (int i = 0; i < 8; i++)
            gsum = fmaf(mk[i], ev[i] + tr_s[yt[i] * 16 + yp[i]], gsum);
    }
#pragma unroll
    for (int s = 16; s; s >>= 1)
        gsum += __shfl_xor_sync(0xFFFFFFFFu, gsum, s);
    const float gold = gsum + tr_s[STOP_ID * 16 + yrow[(len - 1) << ysh]];

    // split: forward does m steps, backward does len-1-m steps
    const int m    = (len - 1) >> 1;
    const int cntF = m;
    const int cntB = len - 1 - m;
    const int cnt  = grp ? cntB : cntF;          // this lane's active steps
    const int trip = (max(cntF, cntB) + 7) & ~7; // warp-uniform

    for (int s0 = 0; s0 < trip; s0 += 8) {
        unsigned mu = 0u;       // stale-by-1 lane-local max of exchanged bits

#pragma unroll
        for (int u = 0; u < 8; u++) {
            const bool act = (s0 + u) < cnt;     // per-lane FSEL
            float* buf = pbuf[u & 1][wid][grp];
            buf[j] = p;
            __syncwarp();
            const ulonglong2* bp = (const ulonglong2*)buf;
            const ulonglong2 v0 = bp[0];
            const ulonglong2 v1 = bp[1];
            const ulonglong2 v2 = bp[2];
            const ulonglong2 v3 = bp[3];

            u64 a0 = fma2(v0.y, EtrP[1], mul2(v0.x, EtrP[0]));
            u64 a1 = fma2(v1.y, EtrP[3], mul2(v1.x, EtrP[2]));
            u64 a2 = fma2(v2.y, EtrP[5], mul2(v2.x, EtrP[4]));
            u64 a3 = fma2(v3.y, EtrP[7], mul2(v3.x, EtrP[6]));
            float S = hadd2(add2(add2(a0, a1), add2(a2, a3)));
            float pn = S * ehq[u];
            p = act ? pn : p;

            // rotate emit pipeline (off the dependency chain)
            ehq[u] = __expf(hb[u]);
            hb[u] = hrow[max(ebase + esgn * (s0 + u + 16), 0) * 16 + j];

            if (u == 7) {
                unsigned m0 = max((unsigned)v0.x, (unsigned)(v0.x >> 32));
                unsigned m1 = max((unsigned)v0.y, (unsigned)(v0.y >> 32));
                unsigned m2 = max((unsigned)v1.x, (unsigned)(v1.x >> 32));
                unsigned m3 = max((unsigned)v1.y, (unsigned)(v1.y >> 32));
                unsigned m4 = max((unsigned)v2.x, (unsigned)(v2.x >> 32));
                unsigned m5 = max((unsigned)v2.y, (unsigned)(v2.y >> 32));
                unsigned m6 = max((unsigned)v3.x, (unsigned)(v3.x >> 32));
                unsigned m7 = max((unsigned)v3.y, (unsigned)(v3.y >> 32));
                mu = max(max(max(m0, m1), max(m2, m3)),
                         max(max(m4, m5), max(m6, m7)));
            }
        }
        // exponent-only renorm: exact power-of-2 scaling
        int me = (int)(mu >> 23);
        me = (me < 1) ? 1 : me;
        float scale = __uint_as_float((unsigned)(254 - me) << 23);  // 2^(127-me)
        C += (float)(me - 127) * 0.6931471805599453f;
        p *= scale;
    }

    // ---- stitch: score = C_f + C_b + ln( sum_j w_m[j] * (Etr p_m)[j] ) ----
    {
        float* buf = pbuf[0][wid][grp];
        buf[j] = p;
        __syncwarp();
        const ulonglong2* bp = (const ulonglong2*)buf;
        const ulonglong2 v0 = bp[0];
        const ulonglong2 v1 = bp[1];
        const ulonglong2 v2 = bp[2];
        const ulonglong2 v3 = bp[3];
        u64 a0 = fma2(v0.y, EtrP[1], mul2(v0.x, EtrP[0]));
        u64 a1 = fma2(v1.y, EtrP[3], mul2(v1.x, EtrP[2]));
        u64 a2 = fma2(v2.y, EtrP[5], mul2(v2.x, EtrP[4]));
        u64 a3 = fma2(v3.y, EtrP[7], mul2(v3.x, EtrP[6]));
        float S = hadd2(add2(add2(a0, a1), add2(a2, a3)));  // fwd lanes: (Etr p_m)[j]

        float wsw = __shfl_xor_sync(0xFFFFFFFFu, p, 16);    // fwd lane j <- w_m[j]
        float Csw = __shfl_xor_sync(0xFFFFFFFFu, C, 16);    // fwd lane <- C_b

        float v = S * wsw;
#pragma unroll
        for (int s = 8; s; s >>= 1)
            v += __shfl_xor_sync(0xFFFFFFFFu, v, s, 16);

        if (lane == 0) {
            float fwd = C + Csw + __logf(v);
            g_row_out[row] = fwd - gold;
        }
    }

    // ---- last-block mean reduction ----
    __threadfence();
    __syncthreads();
    if (tid == 0) {
        int old = atomicAdd(&g_ctr, 1);
        s_last = (old == gridDim.x - 1);
    }
    __syncthreads();
    if (s_last) {
        float s = 0.f;
#pragma unroll
        for (int i = 0; i < BROWS / 128; i++)
            s += g_row_out[tid + i * 128];
#pragma unroll
        for (int sft = 16; sft; sft >>= 1)
            s += __shfl_xor_sync(0xFFFFFFFFu, s, sft);
        if ((tid & 31) == 0) s_red[tid >> 5] = s;
        __syncthreads();
        if (tid == 0) {
            float tot = s_red[0] + s_red[1] + s_red[2] + s_red[3];
            out[0] = tot * (1.0f / (float)BROWS);
            g_ctr = 0;   // reset for next graph replay
        }
    }
}

// ---------------------------------------------------------------------------
extern "C" void kernel_launch(void* const* d_in, const int* in_sizes, int n_in,
                              void* d_out, int out_size) {
    const float* h     = (const float*)d_in[0];
    const int*   y     = (const int*)d_in[1];
    const float* mask  = (const float*)d_in[2];
    const float* trans = (const float*)d_in[3];
    float* out = (float*)d_out;

    crf_fused_kernel<<<BROWS / 4, 128>>>(h, y, mask, trans, out);
}